// round 12
// baseline (speedup 1.0000x reference)
#include <cuda_runtime.h>
#include <cstdint>
#include <cstddef>

// ---------------- problem constants ----------------
constexpr int N_NODES = 100000;
constexpr int IN_C    = 256;
constexpr int HID_C   = 128;
constexpr int OUT_C   = 64;
constexpr int N_EDGES = 1600000;
constexpr int N_LBL   = 200000;

// ---------------- scratch (device globals) ----------------------------------
__device__ __align__(16) int   g_deg   [N_NODES];
__device__ __align__(16) int   g_rowptr[N_NODES + 1];
__device__ __align__(16) int   g_cursor[N_NODES];
__device__ __align__(16) int   g_col   [N_EDGES];
__device__ __align__(16) float g_dinv  [N_NODES];
__device__ __align__(16) float g_bufA[(size_t)N_NODES * HID_C]; // h0, then h0*dinv
__device__ __align__(16) float g_h   [(size_t)N_NODES * HID_C]; // h (post layer 1)
__device__ __align__(16) float g_z0s [(size_t)N_NODES * OUT_C]; // (h@W2)*dinv
__device__ __align__(16) float g_z   [(size_t)N_NODES * OUT_C]; // final node embeddings

// ---------------- CSR build --------------------------------------------------
__global__ void deg_count_kernel(const int* __restrict__ ei) {
    const int idx    = blockIdx.x * blockDim.x + threadIdx.x;
    const int stride = gridDim.x * blockDim.x;
    for (int e = idx; e < N_EDGES; e += stride)
        atomicAdd(&g_deg[__ldg(&ei[N_EDGES + e])], 1);
}

constexpr int SCAN_T  = 1024;
constexpr int SCAN_CH = (N_NODES + SCAN_T - 1) / SCAN_T;   // 98

__global__ void rowptr_kernel() {
    __shared__ int part[SCAN_T];
    const int t    = threadIdx.x;
    const int base = t * SCAN_CH;
    int sum = 0;
    for (int i = 0; i < SCAN_CH; i++) {
        int idx = base + i;
        if (idx < N_NODES) sum += g_deg[idx];
    }
    part[t] = sum;
    __syncthreads();
#pragma unroll
    for (int off = 1; off < SCAN_T; off <<= 1) {
        int v = (t >= off) ? part[t - off] : 0;
        __syncthreads();
        part[t] += v;
        __syncthreads();
    }
    int run = part[t] - sum;
    for (int i = 0; i < SCAN_CH; i++) {
        int idx = base + i;
        if (idx < N_NODES) {
            g_rowptr[idx] = run;
            g_cursor[idx] = run;
            run += g_deg[idx];
        }
    }
    if (t == 0) g_rowptr[N_NODES] = part[SCAN_T - 1];
}

__global__ void fill_kernel(const int* __restrict__ ei) {
    const int idx    = blockIdx.x * blockDim.x + threadIdx.x;
    const int stride = gridDim.x * blockDim.x;
    for (int e = idx; e < N_EDGES; e += stride) {
        int s = __ldg(&ei[e]);
        int d = __ldg(&ei[N_EDGES + e]);
        int pos = atomicAdd(&g_cursor[d], 1);
        g_col[pos] = s;
    }
}

__global__ void dinv_kernel() {
    const int i = blockIdx.x * blockDim.x + threadIdx.x;
    if (i < N_NODES) g_dinv[i] = rsqrtf((float)g_deg[i] + 1.0f);  // +1 self-loop
}

// ---------------- h0 row scaling: bufA[i,:] *= dinv[i] -----------------------
__global__ void scale_h0_kernel() {
    const int idx = blockIdx.x * blockDim.x + threadIdx.x;
    const int n4  = N_NODES * HID_C / 4;
    if (idx >= n4) return;
    const int i = idx >> 5;               // /(HID_C/4)
    float  s = g_dinv[i];
    float4 v = reinterpret_cast<const float4*>(g_bufA)[idx];
    v.x *= s; v.y *= s; v.z *= s; v.w *= s;
    reinterpret_cast<float4*>(g_bufA)[idx] = v;
}

// ---------------- double-buffered fp32 GEMM ---------------------------------
// out[r,:] = SCALE ? dinv[r]*(X[r,:]@W) : X[r,:]@W
template <int BN, int K, bool SCALE>
__device__ __forceinline__ void gemm_core(const float* __restrict__ X,
                                          const float* __restrict__ W,
                                          float* __restrict__ out) {
    constexpr int BM  = 128, BK = 16;
    constexpr int TX  = BN / 8;
    constexpr int NT  = 16 * TX;
    constexpr int XLD = BM * BK / NT / 4;
    constexpr int WLD = BK * BN / NT / 4;
    constexpr int NTILE = K / BK;

    __shared__ float xs[2][BK][BM];
    __shared__ float ws[2][BK][BN];

    const int tid  = threadIdx.x;
    const int tx   = tid % TX;
    const int ty   = tid / TX;
    const int row0 = blockIdx.x * BM;

    float4 xreg[XLD], wreg[WLD];

    auto load_tile = [&](int k0) {
#pragma unroll
        for (int i = 0; i < XLD; i++) {
            int f = tid + i * NT;
            int r = f >> 2, kq = f & 3;
            int gr = row0 + r;
            if (gr > N_NODES - 1) gr = N_NODES - 1;
            xreg[i] = *reinterpret_cast<const float4*>(X + (size_t)gr * K + k0 + kq * 4);
        }
#pragma unroll
        for (int i = 0; i < WLD; i++) {
            int f  = tid + i * NT;
            int kr = f / (BN / 4), cq = f % (BN / 4);
            wreg[i] = *reinterpret_cast<const float4*>(W + (size_t)(k0 + kr) * BN + cq * 4);
        }
    };
    auto store_tile = [&](int buf) {
#pragma unroll
        for (int i = 0; i < XLD; i++) {
            int f = tid + i * NT;
            int r = f >> 2, kq = f & 3;
            xs[buf][kq * 4 + 0][r] = xreg[i].x;
            xs[buf][kq * 4 + 1][r] = xreg[i].y;
            xs[buf][kq * 4 + 2][r] = xreg[i].z;
            xs[buf][kq * 4 + 3][r] = xreg[i].w;
        }
#pragma unroll
        for (int i = 0; i < WLD; i++) {
            int f  = tid + i * NT;
            int kr = f / (BN / 4), cq = f % (BN / 4);
            *reinterpret_cast<float4*>(&ws[buf][kr][cq * 4]) = wreg[i];
        }
    };

    float acc[8][8];
#pragma unroll
    for (int i = 0; i < 8; i++)
#pragma unroll
        for (int j = 0; j < 8; j++) acc[i][j] = 0.f;

    load_tile(0);
    store_tile(0);
    __syncthreads();

    for (int t = 0; t < NTILE; t++) {
        const int cur = t & 1;
        if (t + 1 < NTILE) load_tile((t + 1) * BK);

#pragma unroll
        for (int kk = 0; kk < BK; kk++) {
            float a[8], b[8];
            *reinterpret_cast<float4*>(a)     = *reinterpret_cast<const float4*>(&xs[cur][kk][ty * 8]);
            *reinterpret_cast<float4*>(a + 4) = *reinterpret_cast<const float4*>(&xs[cur][kk][ty * 8 + 4]);
            *reinterpret_cast<float4*>(b)     = *reinterpret_cast<const float4*>(&ws[cur][kk][tx * 8]);
            *reinterpret_cast<float4*>(b + 4) = *reinterpret_cast<const float4*>(&ws[cur][kk][tx * 8 + 4]);
#pragma unroll
            for (int i = 0; i < 8; i++)
#pragma unroll
                for (int j = 0; j < 8; j++)
                    acc[i][j] = fmaf(a[i], b[j], acc[i][j]);
        }
        if (t + 1 < NTILE) {
            store_tile((t + 1) & 1);
            __syncthreads();
        }
    }

#pragma unroll
    for (int i = 0; i < 8; i++) {
        int r = row0 + ty * 8 + i;
        if (r < N_NODES) {
            float s = SCALE ? g_dinv[r] : 1.0f;
#pragma unroll
            for (int j = 0; j < 8; j += 4) {
                float4 v;
                v.x = acc[i][j + 0] * s;
                v.y = acc[i][j + 1] * s;
                v.z = acc[i][j + 2] * s;
                v.w = acc[i][j + 3] * s;
                *reinterpret_cast<float4*>(out + (size_t)r * BN + tx * 8 + j) = v;
            }
        }
    }
}

__global__ void __launch_bounds__(256, 2) gemm1_kernel(const float* __restrict__ X,
                                                       const float* __restrict__ W) {
    gemm_core<HID_C, IN_C, false>(X, W, g_bufA);   // unscaled: no dinv dependency
}
__global__ void __launch_bounds__(128, 4) gemm2_kernel(const float* __restrict__ W) {
    gemm_core<OUT_C, HID_C, true>(g_h, W, g_z0s);  // dinv ready by now
}

// ---------------- CSR aggregation, layer 1 (128 feats, warp/node) -----------
__global__ void __launch_bounds__(256) agg128_kernel(const float* __restrict__ b1) {
    const int lane = threadIdx.x & 31;
    const int node = (blockIdx.x * blockDim.x + threadIdx.x) >> 5;
    if (node >= N_NODES) return;
    const int beg = g_rowptr[node];
    const int end = g_rowptr[node + 1];
    const float4* __restrict__ H = reinterpret_cast<const float4*>(g_bufA);

    float4 acc = H[(size_t)node * 32 + lane];   // self (pre-scaled)
    int j = beg;
    for (; j + 7 < end; j += 8) {
        int s[8];
#pragma unroll
        for (int t = 0; t < 8; t++) s[t] = __ldg(&g_col[j + t]);
#pragma unroll
        for (int t = 0; t < 8; t++) {
            float4 v = H[(size_t)s[t] * 32 + lane];
            acc.x += v.x; acc.y += v.y; acc.z += v.z; acc.w += v.w;
        }
    }
    if (j + 3 < end) {
        int s[4];
#pragma unroll
        for (int t = 0; t < 4; t++) s[t] = __ldg(&g_col[j + t]);
#pragma unroll
        for (int t = 0; t < 4; t++) {
            float4 v = H[(size_t)s[t] * 32 + lane];
            acc.x += v.x; acc.y += v.y; acc.z += v.z; acc.w += v.w;
        }
        j += 4;
    }
    for (; j < end; j++) {
        int s = __ldg(&g_col[j]);
        float4 v = H[(size_t)s * 32 + lane];
        acc.x += v.x; acc.y += v.y; acc.z += v.z; acc.w += v.w;
    }
    const float sc = g_dinv[node];
    const float4 b = reinterpret_cast<const float4*>(b1)[lane];
    float4 r;
    r.x = fmaxf(fmaf(sc, acc.x, b.x), 0.f);
    r.y = fmaxf(fmaf(sc, acc.y, b.y), 0.f);
    r.z = fmaxf(fmaf(sc, acc.z, b.z), 0.f);
    r.w = fmaxf(fmaf(sc, acc.w, b.w), 0.f);
    reinterpret_cast<float4*>(g_h)[(size_t)node * 32 + lane] = r;
}

// ---------------- CSR aggregation, layer 2 (64 feats, 16 thr/node) ----------
__global__ void __launch_bounds__(256) agg64_kernel(const float* __restrict__ b2) {
    const int t0   = blockIdx.x * blockDim.x + threadIdx.x;
    const int l    = t0 & 15;
    const int node = t0 >> 4;
    if (node >= N_NODES) return;
    const int beg = g_rowptr[node];
    const int end = g_rowptr[node + 1];
    const float4* __restrict__ Z = reinterpret_cast<const float4*>(g_z0s);

    float4 acc = Z[(size_t)node * 16 + l];
    int j = beg;
    for (; j + 7 < end; j += 8) {
        int s[8];
#pragma unroll
        for (int t = 0; t < 8; t++) s[t] = __ldg(&g_col[j + t]);
#pragma unroll
        for (int t = 0; t < 8; t++) {
            float4 v = Z[(size_t)s[t] * 16 + l];
            acc.x += v.x; acc.y += v.y; acc.z += v.z; acc.w += v.w;
        }
    }
    if (j + 3 < end) {
        int s[4];
#pragma unroll
        for (int t = 0; t < 4; t++) s[t] = __ldg(&g_col[j + t]);
#pragma unroll
        for (int t = 0; t < 4; t++) {
            float4 v = Z[(size_t)s[t] * 16 + l];
            acc.x += v.x; acc.y += v.y; acc.z += v.z; acc.w += v.w;
        }
        j += 4;
    }
    for (; j < end; j++) {
        int s = __ldg(&g_col[j]);
        float4 v = Z[(size_t)s * 16 + l];
        acc.x += v.x; acc.y += v.y; acc.z += v.z; acc.w += v.w;
    }
    const float sc = g_dinv[node];
    const float4 b = reinterpret_cast<const float4*>(b2)[l];
    float4 r;
    r.x = fmaf(sc, acc.x, b.x);
    r.y = fmaf(sc, acc.y, b.y);
    r.z = fmaf(sc, acc.z, b.z);
    r.w = fmaf(sc, acc.w, b.w);
    reinterpret_cast<float4*>(g_z)[(size_t)node * 16 + l] = r;
}

// ---------------- final: out[e] = dot(z[src], z[dst]), 16 thr/edge ----------
__global__ void edge_dot_kernel(const int* __restrict__ eli,
                                float* __restrict__ out) {
    const int t0 = blockIdx.x * blockDim.x + threadIdx.x;
    const int l  = t0 & 15;
    const int e  = t0 >> 4;
    if (e >= N_LBL) return;
    int s = __ldg(&eli[e]);
    int d = __ldg(&eli[N_LBL + e]);
    float4 a = *reinterpret_cast<const float4*>(&g_z[(size_t)s * OUT_C + l * 4]);
    float4 b = *reinterpret_cast<const float4*>(&g_z[(size_t)d * OUT_C + l * 4]);
    float p = a.x * b.x + a.y * b.y + a.z * b.z + a.w * b.w;
#pragma unroll
    for (int o = 8; o > 0; o >>= 1) p += __shfl_down_sync(0xffffffffu, p, o, 16);
    if (l == 0) out[e] = p;
}

// ---------------- launch ----------------------------------------------------
extern "C" void kernel_launch(void* const* d_in, const int* in_sizes, int n_in,
                              void* d_out, int out_size) {
    const float* x   = (const float*)d_in[0];
    const int*   ei  = (const int*)d_in[1];   // int32 (JAX x64 disabled)
    const int*   eli = (const int*)d_in[2];
    const float* W1  = (const float*)d_in[3];
    const float* b1  = (const float*)d_in[4];
    const float* W2  = (const float*)d_in[5];
    const float* b2  = (const float*)d_in[6];
    float*       out = (float*)d_out;

    void* deg_ptr = nullptr;
    cudaGetSymbolAddress(&deg_ptr, g_deg);

    cudaStream_t s2;
    cudaEvent_t  e0, eB;
    cudaStreamCreateWithFlags(&s2, cudaStreamNonBlocking);
    cudaEventCreateWithFlags(&e0, cudaEventDisableTiming);
    cudaEventCreateWithFlags(&eB, cudaEventDisableTiming);

    // fork: entire CSR build + dinv on side stream, hidden under gemm1
    cudaEventRecord(e0, 0);
    cudaStreamWaitEvent(s2, e0, 0);
    cudaMemsetAsync(deg_ptr, 0, N_NODES * sizeof(int), s2);
    deg_count_kernel<<<2048, 256, 0, s2>>>(ei);
    rowptr_kernel<<<1, SCAN_T, 0, s2>>>();
    fill_kernel<<<2048, 256, 0, s2>>>(ei);
    dinv_kernel<<<(N_NODES + 255) / 256, 256, 0, s2>>>();
    cudaEventRecord(eB, s2);

    // main: gemm1 (no dependencies) from t=0
    gemm1_kernel<<<(N_NODES + 127) / 128, 256>>>(x, W1);
    cudaStreamWaitEvent(0, eB, 0);             // join CSR + dinv
    scale_h0_kernel<<<(N_NODES * HID_C / 4 + 255) / 256, 256>>>();

    agg128_kernel<<<(N_NODES * 32 + 255) / 256, 256>>>(b1);
    gemm2_kernel<<<(N_NODES + 127) / 128, 128>>>(W2);
    agg64_kernel<<<(N_NODES * 16 + 255) / 256, 256>>>(b2);
    edge_dot_kernel<<<(N_LBL * 16 + 255) / 256, 256>>>(eli, out);
}

// round 13
// speedup vs baseline: 1.4302x; 1.4302x over previous
#include <cuda_runtime.h>
#include <cstdint>
#include <cstddef>

// ---------------- problem constants ----------------
constexpr int N_NODES = 100000;
constexpr int IN_C    = 256;
constexpr int HID_C   = 128;
constexpr int OUT_C   = 64;
constexpr int N_EDGES = 1600000;
constexpr int N_LBL   = 200000;

// ---------------- scratch (device globals) ----------------------------------
__device__ __align__(16) int   g_deg   [N_NODES];
__device__ __align__(16) int   g_rowptr[N_NODES + 1];
__device__ __align__(16) int   g_cursor[N_NODES];
__device__ __align__(16) int   g_col   [N_EDGES];
__device__ __align__(16) float g_dinv  [N_NODES];
__device__ __align__(16) float g_bufA[(size_t)N_NODES * HID_C]; // h0s = (x@W1)*dinv
__device__ __align__(16) float g_h   [(size_t)N_NODES * HID_C]; // h (post layer 1)
__device__ __align__(16) float g_z0s [(size_t)N_NODES * OUT_C]; // (h@W2)*dinv
__device__ __align__(16) float g_z   [(size_t)N_NODES * OUT_C]; // final node embeddings

// ---------------- CSR build --------------------------------------------------
__global__ void deg_count_kernel(const int* __restrict__ ei) {
    const int idx    = blockIdx.x * blockDim.x + threadIdx.x;
    const int stride = gridDim.x * blockDim.x;
    for (int e = idx; e < N_EDGES; e += stride)
        atomicAdd(&g_deg[__ldg(&ei[N_EDGES + e])], 1);
}

constexpr int SCAN_T  = 1024;
constexpr int SCAN_CH = (N_NODES + SCAN_T - 1) / SCAN_T;   // 98

__global__ void rowptr_kernel() {
    __shared__ int part[SCAN_T];
    const int t    = threadIdx.x;
    const int base = t * SCAN_CH;
    int sum = 0;
    for (int i = 0; i < SCAN_CH; i++) {
        int idx = base + i;
        if (idx < N_NODES) sum += g_deg[idx];
    }
    part[t] = sum;
    __syncthreads();
#pragma unroll
    for (int off = 1; off < SCAN_T; off <<= 1) {
        int v = (t >= off) ? part[t - off] : 0;
        __syncthreads();
        part[t] += v;
        __syncthreads();
    }
    int run = part[t] - sum;
    for (int i = 0; i < SCAN_CH; i++) {
        int idx = base + i;
        if (idx < N_NODES) {
            g_rowptr[idx] = run;
            g_cursor[idx] = run;
            run += g_deg[idx];
        }
    }
    if (t == 0) g_rowptr[N_NODES] = part[SCAN_T - 1];
}

__global__ void fill_kernel(const int* __restrict__ ei) {
    const int idx    = blockIdx.x * blockDim.x + threadIdx.x;
    const int stride = gridDim.x * blockDim.x;
    for (int e = idx; e < N_EDGES; e += stride) {
        int s = __ldg(&ei[e]);
        int d = __ldg(&ei[N_EDGES + e]);
        int pos = atomicAdd(&g_cursor[d], 1);
        g_col[pos] = s;
    }
}

__global__ void dinv_kernel() {
    const int i = blockIdx.x * blockDim.x + threadIdx.x;
    if (i < N_NODES) g_dinv[i] = rsqrtf((float)g_deg[i] + 1.0f);  // +1 self-loop
}

// ---------------- double-buffered fp32 GEMM, dinv-scaled epilogue -----------
// out[r,:] = dinv[r] * (X[r,:] @ W)
template <int BN, int K>
__device__ __forceinline__ void gemm_core(const float* __restrict__ X,
                                          const float* __restrict__ W,
                                          float* __restrict__ out) {
    constexpr int BM  = 128, BK = 16;
    constexpr int TX  = BN / 8;
    constexpr int NT  = 16 * TX;
    constexpr int XLD = BM * BK / NT / 4;
    constexpr int WLD = BK * BN / NT / 4;
    constexpr int NTILE = K / BK;

    __shared__ float xs[2][BK][BM];
    __shared__ float ws[2][BK][BN];

    const int tid  = threadIdx.x;
    const int tx   = tid % TX;
    const int ty   = tid / TX;
    const int row0 = blockIdx.x * BM;

    float4 xreg[XLD], wreg[WLD];

    auto load_tile = [&](int k0) {
#pragma unroll
        for (int i = 0; i < XLD; i++) {
            int f = tid + i * NT;
            int r = f >> 2, kq = f & 3;
            int gr = row0 + r;
            if (gr > N_NODES - 1) gr = N_NODES - 1;   // clamp; dup row discarded
            xreg[i] = *reinterpret_cast<const float4*>(X + (size_t)gr * K + k0 + kq * 4);
        }
#pragma unroll
        for (int i = 0; i < WLD; i++) {
            int f  = tid + i * NT;
            int kr = f / (BN / 4), cq = f % (BN / 4);
            wreg[i] = *reinterpret_cast<const float4*>(W + (size_t)(k0 + kr) * BN + cq * 4);
        }
    };
    auto store_tile = [&](int buf) {
#pragma unroll
        for (int i = 0; i < XLD; i++) {
            int f = tid + i * NT;
            int r = f >> 2, kq = f & 3;
            xs[buf][kq * 4 + 0][r] = xreg[i].x;
            xs[buf][kq * 4 + 1][r] = xreg[i].y;
            xs[buf][kq * 4 + 2][r] = xreg[i].z;
            xs[buf][kq * 4 + 3][r] = xreg[i].w;
        }
#pragma unroll
        for (int i = 0; i < WLD; i++) {
            int f  = tid + i * NT;
            int kr = f / (BN / 4), cq = f % (BN / 4);
            *reinterpret_cast<float4*>(&ws[buf][kr][cq * 4]) = wreg[i];
        }
    };

    float acc[8][8];
#pragma unroll
    for (int i = 0; i < 8; i++)
#pragma unroll
        for (int j = 0; j < 8; j++) acc[i][j] = 0.f;

    load_tile(0);
    store_tile(0);
    __syncthreads();

    for (int t = 0; t < NTILE; t++) {
        const int cur = t & 1;
        if (t + 1 < NTILE) load_tile((t + 1) * BK);

#pragma unroll
        for (int kk = 0; kk < BK; kk++) {
            float a[8], b[8];
            *reinterpret_cast<float4*>(a)     = *reinterpret_cast<const float4*>(&xs[cur][kk][ty * 8]);
            *reinterpret_cast<float4*>(a + 4) = *reinterpret_cast<const float4*>(&xs[cur][kk][ty * 8 + 4]);
            *reinterpret_cast<float4*>(b)     = *reinterpret_cast<const float4*>(&ws[cur][kk][tx * 8]);
            *reinterpret_cast<float4*>(b + 4) = *reinterpret_cast<const float4*>(&ws[cur][kk][tx * 8 + 4]);
#pragma unroll
            for (int i = 0; i < 8; i++)
#pragma unroll
                for (int j = 0; j < 8; j++)
                    acc[i][j] = fmaf(a[i], b[j], acc[i][j]);
        }
        if (t + 1 < NTILE) {
            store_tile((t + 1) & 1);
            __syncthreads();
        }
    }

#pragma unroll
    for (int i = 0; i < 8; i++) {
        int r = row0 + ty * 8 + i;
        if (r < N_NODES) {
            float s = g_dinv[r];
#pragma unroll
            for (int j = 0; j < 8; j += 4) {
                float4 v;
                v.x = acc[i][j + 0] * s;
                v.y = acc[i][j + 1] * s;
                v.z = acc[i][j + 2] * s;
                v.w = acc[i][j + 3] * s;
                *reinterpret_cast<float4*>(out + (size_t)r * BN + tx * 8 + j) = v;
            }
        }
    }
}

__global__ void __launch_bounds__(256, 2) gemm1_kernel(const float* __restrict__ X,
                                                       const float* __restrict__ W) {
    gemm_core<HID_C, IN_C>(X, W, g_bufA);
}
__global__ void __launch_bounds__(128, 4) gemm2_kernel(const float* __restrict__ W) {
    gemm_core<OUT_C, HID_C>(g_h, W, g_z0s);
}

// ---------------- CSR aggregation, layer 1 (128 feats, warp/node) -----------
// h[i] = relu(dinv[i] * (h0s[i] + sum_{s in N(i)} h0s[s]) + b1)   [h0s pre-scaled]
__global__ void __launch_bounds__(256) agg128_kernel(const float* __restrict__ b1) {
    const int lane = threadIdx.x & 31;
    const int node = (blockIdx.x * blockDim.x + threadIdx.x) >> 5;
    if (node >= N_NODES) return;
    const int beg = g_rowptr[node];
    const int end = g_rowptr[node + 1];
    const float4* __restrict__ H = reinterpret_cast<const float4*>(g_bufA);

    float4 acc = H[(size_t)node * 32 + lane];   // self (pre-scaled)
    int j = beg;
    for (; j + 7 < end; j += 8) {
        int s[8];
#pragma unroll
        for (int t = 0; t < 8; t++) s[t] = __ldg(&g_col[j + t]);
#pragma unroll
        for (int t = 0; t < 8; t++) {
            float4 v = H[(size_t)s[t] * 32 + lane];
            acc.x += v.x; acc.y += v.y; acc.z += v.z; acc.w += v.w;
        }
    }
    if (j + 3 < end) {
        int s[4];
#pragma unroll
        for (int t = 0; t < 4; t++) s[t] = __ldg(&g_col[j + t]);
#pragma unroll
        for (int t = 0; t < 4; t++) {
            float4 v = H[(size_t)s[t] * 32 + lane];
            acc.x += v.x; acc.y += v.y; acc.z += v.z; acc.w += v.w;
        }
        j += 4;
    }
    for (; j < end; j++) {
        int s = __ldg(&g_col[j]);
        float4 v = H[(size_t)s * 32 + lane];
        acc.x += v.x; acc.y += v.y; acc.z += v.z; acc.w += v.w;
    }
    const float sc = g_dinv[node];
    const float4 b = reinterpret_cast<const float4*>(b1)[lane];
    float4 r;
    r.x = fmaxf(fmaf(sc, acc.x, b.x), 0.f);
    r.y = fmaxf(fmaf(sc, acc.y, b.y), 0.f);
    r.z = fmaxf(fmaf(sc, acc.z, b.z), 0.f);
    r.w = fmaxf(fmaf(sc, acc.w, b.w), 0.f);
    reinterpret_cast<float4*>(g_h)[(size_t)node * 32 + lane] = r;
}

// ---------------- CSR aggregation, layer 2 (64 feats, 16 thr/node) ----------
__global__ void __launch_bounds__(256) agg64_kernel(const float* __restrict__ b2) {
    const int t0   = blockIdx.x * blockDim.x + threadIdx.x;
    const int l    = t0 & 15;
    const int node = t0 >> 4;
    if (node >= N_NODES) return;
    const int beg = g_rowptr[node];
    const int end = g_rowptr[node + 1];
    const float4* __restrict__ Z = reinterpret_cast<const float4*>(g_z0s);

    float4 acc = Z[(size_t)node * 16 + l];
    int j = beg;
    for (; j + 7 < end; j += 8) {
        int s[8];
#pragma unroll
        for (int t = 0; t < 8; t++) s[t] = __ldg(&g_col[j + t]);
#pragma unroll
        for (int t = 0; t < 8; t++) {
            float4 v = Z[(size_t)s[t] * 16 + l];
            acc.x += v.x; acc.y += v.y; acc.z += v.z; acc.w += v.w;
        }
    }
    if (j + 3 < end) {
        int s[4];
#pragma unroll
        for (int t = 0; t < 4; t++) s[t] = __ldg(&g_col[j + t]);
#pragma unroll
        for (int t = 0; t < 4; t++) {
            float4 v = Z[(size_t)s[t] * 16 + l];
            acc.x += v.x; acc.y += v.y; acc.z += v.z; acc.w += v.w;
        }
        j += 4;
    }
    for (; j < end; j++) {
        int s = __ldg(&g_col[j]);
        float4 v = Z[(size_t)s * 16 + l];
        acc.x += v.x; acc.y += v.y; acc.z += v.z; acc.w += v.w;
    }
    const float sc = g_dinv[node];
    const float4 b = reinterpret_cast<const float4*>(b2)[l];
    float4 r;
    r.x = fmaf(sc, acc.x, b.x);
    r.y = fmaf(sc, acc.y, b.y);
    r.z = fmaf(sc, acc.z, b.z);
    r.w = fmaf(sc, acc.w, b.w);
    reinterpret_cast<float4*>(g_z)[(size_t)node * 16 + l] = r;
}

// ---------------- final: out[e] = dot(z[src], z[dst]), 16 thr/edge ----------
__global__ void edge_dot_kernel(const int* __restrict__ eli,
                                float* __restrict__ out) {
    const int t0 = blockIdx.x * blockDim.x + threadIdx.x;
    const int l  = t0 & 15;
    const int e  = t0 >> 4;
    if (e >= N_LBL) return;
    int s = __ldg(&eli[e]);
    int d = __ldg(&eli[N_LBL + e]);
    float4 a = *reinterpret_cast<const float4*>(&g_z[(size_t)s * OUT_C + l * 4]);
    float4 b = *reinterpret_cast<const float4*>(&g_z[(size_t)d * OUT_C + l * 4]);
    float p = a.x * b.x + a.y * b.y + a.z * b.z + a.w * b.w;
#pragma unroll
    for (int o = 8; o > 0; o >>= 1) p += __shfl_down_sync(0xffffffffu, p, o, 16);
    if (l == 0) out[e] = p;
}

// ---------------- launch ----------------------------------------------------
extern "C" void kernel_launch(void* const* d_in, const int* in_sizes, int n_in,
                              void* d_out, int out_size) {
    const float* x   = (const float*)d_in[0];
    const int*   ei  = (const int*)d_in[1];   // int32 (JAX x64 disabled)
    const int*   eli = (const int*)d_in[2];
    const float* W1  = (const float*)d_in[3];
    const float* b1  = (const float*)d_in[4];
    const float* W2  = (const float*)d_in[5];
    const float* b2  = (const float*)d_in[6];
    float*       out = (float*)d_out;

    void* deg_ptr = nullptr;
    cudaGetSymbolAddress(&deg_ptr, g_deg);

    cudaStream_t s2;
    cudaEvent_t  eA, eB;
    cudaStreamCreateWithFlags(&s2, cudaStreamNonBlocking);
    cudaEventCreateWithFlags(&eA, cudaEventDisableTiming);
    cudaEventCreateWithFlags(&eB, cudaEventDisableTiming);

    // main: degree (needed by both dinv and rowptr) — round-8 structure
    cudaMemsetAsync(deg_ptr, 0, N_NODES * sizeof(int), 0);
    deg_count_kernel<<<2048, 256>>>(ei);
    cudaEventRecord(eA, 0);

    // side: rowptr + fill, concurrent with dinv + gemm1 (light enough to hide)
    cudaStreamWaitEvent(s2, eA, 0);
    rowptr_kernel<<<1, SCAN_T, 0, s2>>>();
    fill_kernel<<<2048, 256, 0, s2>>>(ei);
    cudaEventRecord(eB, s2);

    // main: dinv -> gemm1 (dinv-scaled epilogue)
    dinv_kernel<<<(N_NODES + 255) / 256, 256>>>();
    gemm1_kernel<<<(N_NODES + 127) / 128, 256>>>(x, W1);
    cudaStreamWaitEvent(0, eB, 0);   // join CSR before aggregation

    agg128_kernel<<<(N_NODES * 32 + 255) / 256, 256>>>(b1);
    gemm2_kernel<<<(N_NODES + 127) / 128, 128>>>(W2);
    agg64_kernel<<<(N_NODES * 16 + 255) / 256, 256>>>(b2);
    edge_dot_kernel<<<(N_LBL * 16 + 255) / 256, 256>>>(eli, out);
}